// round 8
// baseline (speedup 1.0000x reference)
#include <cuda_runtime.h>
#include <cuda_bf16.h>
#include <cstdint>
#include <math.h>

#define B_N   16384
#define K_N   50
#define V_N   100000
#define BK_N  (B_N * K_N)          // 819200
#define NTILE (BK_N / 128)         // 6400 tiles of 128 pairs
#define VTILE (V_N / 16)           // 6250 vocab warp-tiles

typedef unsigned int u32;
typedef unsigned short u16;

// ---------------------------------------------------------------------------
// Device scratch
// ---------------------------------------------------------------------------
__device__ float g_P  [(size_t)V_N * 64];
__device__ float g_A1B[(size_t)V_N * 64];
__device__ float g_O  [(size_t)BK_N * 64];
__device__ float g_S  [(size_t)BK_N];
// bf16 fragments for k_pre: [L:2][part:2][kt:4][nt:8][lane:32][reg:2]
__device__ u32   g_Wf [2 * 4096];
// int8 fragments for k_main: [L:3][w:2][kt:2][nt:8][lane:32][reg:2]
__device__ u32   g_WfI[3 * 2048];
__device__ float g_Wsc[3 * 64];           // per-col dequant scale maxW/127

// ---------------------------------------------------------------------------
// helpers
// ---------------------------------------------------------------------------
__device__ __forceinline__ u32 pack_bf16x2(float lo, float hi) {
    u32 d;
    asm("cvt.rn.bf16x2.f32 %0, %1, %2;" : "=r"(d) : "f"(hi), "f"(lo));
    return d;
}
__device__ __forceinline__ void split2(float v0, float v1, u32& h, u32& l) {
    h = pack_bf16x2(v0, v1);
    const float r0 = v0 - __uint_as_float(h << 16);
    const float r1 = v1 - __uint_as_float(h & 0xFFFF0000u);
    l = pack_bf16x2(r0, r1);
}
__device__ __forceinline__ void mma16816(float& d0, float& d1, float& d2, float& d3,
                                         u32 a0, u32 a1, u32 a2, u32 a3,
                                         u32 b0, u32 b1) {
    asm("mma.sync.aligned.m16n8k16.row.col.f32.bf16.bf16.f32 "
        "{%0,%1,%2,%3}, {%4,%5,%6,%7}, {%8,%9}, {%0,%1,%2,%3};"
        : "+f"(d0), "+f"(d1), "+f"(d2), "+f"(d3)
        : "r"(a0), "r"(a1), "r"(a2), "r"(a3), "r"(b0), "r"(b1));
}
// int8 m16n8k32 MMA, s32 accumulate (sm_80+ baseline)
__device__ __forceinline__ void imma16832(int& d0, int& d1, int& d2, int& d3,
                                          u32 a0, u32 a1, u32 a2, u32 a3,
                                          u32 b0, u32 b1) {
    asm("mma.sync.aligned.m16n8k32.row.col.s32.s8.s8.s32 "
        "{%0,%1,%2,%3}, {%4,%5,%6,%7}, {%8,%9}, {%0,%1,%2,%3};"
        : "+r"(d0), "+r"(d1), "+r"(d2), "+r"(d3)
        : "r"(a0), "r"(a1), "r"(a2), "r"(a3), "r"(b0), "r"(b1));
}

// ---------------------------------------------------------------------------
// Kernel 0a: bf16 B-fragments for k_pre (w1W[0:64], a1W[64:128])
// ---------------------------------------------------------------------------
__global__ void __launch_bounds__(256) k_wfragB(const float* __restrict__ w1W,
                                                const float* __restrict__ a1W)
{
    const int idx = blockIdx.x * 256 + threadIdx.x;   // 2*4*8*32 = 2048
    if (idx >= 2048) return;
    const int lane = idx & 31;
    const int nt   = (idx >> 5) & 7;
    const int kt   = (idx >> 8) & 3;
    const int L    = idx >> 10;

    const float* W = (L == 0) ? w1W : (a1W + 4096);
    const int n  = nt * 8 + (lane >> 2);
    const int k0 = kt * 16 + (lane & 3) * 2;

    u32 h0, l0, h1, l1;
    split2(W[k0*64+n],     W[(k0+1)*64+n], h0, l0);
    split2(W[(k0+8)*64+n], W[(k0+9)*64+n], h1, l1);

    const int base = L * 4096;
    const int fhi = base + ((kt*8 + nt)*32 + lane)*2;
    const int flo = base + 2048 + ((kt*8 + nt)*32 + lane)*2;
    g_Wf[fhi] = h0;  g_Wf[fhi+1] = h1;
    g_Wf[flo] = l0;  g_Wf[flo+1] = l1;
}

// ---------------------------------------------------------------------------
// Kernel 0b: int8 two-term quantized B-fragments for layers 2..4.
// qW = W*(127/maxcol); w1 = rn(qW); w2 = clamp(rn((qW-w1)*256)).
// Fragment (m16n8k32 row.col): n = nt*8+lane/4; reg r: k = kt*32+r*16+(lane%4)*4+{0..3}
// ---------------------------------------------------------------------------
__global__ void __launch_bounds__(64) k_wfragI(const float* __restrict__ w2W,
                                               const float* __restrict__ a1W,
                                               const float* __restrict__ a2W)
{
    __shared__ signed char sq1[64*64];
    __shared__ signed char sq2[64*64];
    const int L = blockIdx.x;
    const float* W = (L == 0) ? w2W : (L == 1) ? a1W : a2W;
    const int tid = threadIdx.x;

    // thread n: quantize its column
    {
        const int n = tid;
        float m = 0.f;
        for (int k = 0; k < 64; k++) m = fmaxf(m, fabsf(W[k*64+n]));
        g_Wsc[L*64+n] = m * (1.f/127.f);
        const float inv = (m > 0.f) ? 127.f/m : 0.f;
        for (int k = 0; k < 64; k++) {
            const float q = W[k*64+n] * inv;
            const int i1 = __float2int_rn(q);
            float r = (q - (float)i1) * 256.f;
            r = fminf(fmaxf(r, -128.f), 127.f);
            const int i2 = __float2int_rn(r);
            sq1[k*64+n] = (signed char)i1;
            sq2[k*64+n] = (signed char)i2;
        }
    }
    __syncthreads();

    for (int idx = tid; idx < 2048; idx += 64) {
        const int r    = idx & 1;
        const int lane = (idx >> 1) & 31;
        const int nt   = (idx >> 6) & 7;
        const int kt   = (idx >> 9) & 1;
        const int w    = (idx >> 10) & 1;
        const signed char* q = w ? sq2 : sq1;
        const int k = kt*32 + r*16 + (lane & 3)*4;
        const int n = nt*8 + (lane >> 2);
        u32 b = 0;
        #pragma unroll
        for (int j = 0; j < 4; j++)
            b |= ((u32)(unsigned char)q[(k+j)*64 + n]) << (8*j);
        g_WfI[L*2048 + idx] = b;
    }
}

// ---------------------------------------------------------------------------
// Kernel 1: HMMA per-vocab precompute of P and A1B (proven bf16 path)
// ---------------------------------------------------------------------------
__device__ __forceinline__ void gemm64(float* D, const u32* ah, const u32* al,
                                       const u32* sBFL, int lane)
{
    #pragma unroll
    for (int nt = 0; nt < 8; nt++) {
        float d0=0.f,d1=0.f,d2=0.f,d3=0.f;
        #pragma unroll
        for (int kt = 0; kt < 4; kt++) {
            const u32* bp = sBFL + (kt*8 + nt)*64 + lane*2;
            const uint2 bh = *reinterpret_cast<const uint2*>(bp);
            const uint2 bl = *reinterpret_cast<const uint2*>(bp + 2048);
            mma16816(d0,d1,d2,d3, ah[kt*4],ah[kt*4+1],ah[kt*4+2],ah[kt*4+3], bh.x,bh.y);
            mma16816(d0,d1,d2,d3, al[kt*4],al[kt*4+1],al[kt*4+2],al[kt*4+3], bh.x,bh.y);
            mma16816(d0,d1,d2,d3, ah[kt*4],ah[kt*4+1],ah[kt*4+2],ah[kt*4+3], bl.x,bl.y);
        }
        D[nt*4+0]=d0; D[nt*4+1]=d1; D[nt*4+2]=d2; D[nt*4+3]=d3;
    }
}

__global__ void __launch_bounds__(256) k_pre(const float* __restrict__ u2e)
{
    __shared__ u32 sBF[8192];
    const int tid = threadIdx.x;
    {
        const uint4* src = reinterpret_cast<const uint4*>(g_Wf);
        uint4* dst = reinterpret_cast<uint4*>(sBF);
        for (int i = tid; i < 2048; i += 256) dst[i] = src[i];
    }
    __syncthreads();

    const int wid  = tid >> 5;
    const int lane = tid & 31;
    const int g    = lane >> 2;
    const int q2   = (lane & 3) << 1;

    const int wt = blockIdx.x * 8 + wid;
    if (wt >= VTILE) return;
    const int v0 = wt * 16 + g;
    const int v1 = v0 + 8;

    u32 ah[16], al[16];
    #pragma unroll
    for (int rr = 0; rr < 2; rr++) {
        const float* Mr = u2e + (size_t)(wt*16 + g + rr*8) * 64;
        #pragma unroll
        for (int kt = 0; kt < 4; kt++) {
            const int c0 = kt*16 + q2;
            const float2 pa = *reinterpret_cast<const float2*>(Mr + c0);
            const float2 pb = *reinterpret_cast<const float2*>(Mr + c0 + 8);
            split2(pa.x, pa.y, ah[kt*4 + rr],     al[kt*4 + rr]);
            split2(pb.x, pb.y, ah[kt*4 + 2 + rr], al[kt*4 + 2 + rr]);
        }
    }

    float D[32];
    gemm64(D, ah, al, sBF, lane);
    #pragma unroll
    for (int nt = 0; nt < 8; nt++) {
        const int c0 = nt*8 + q2;
        *reinterpret_cast<float2*>(g_P + (size_t)v0*64 + c0) = make_float2(D[nt*4+0], D[nt*4+1]);
        *reinterpret_cast<float2*>(g_P + (size_t)v1*64 + c0) = make_float2(D[nt*4+2], D[nt*4+3]);
    }
    gemm64(D, ah, al, sBF + 4096, lane);
    #pragma unroll
    for (int nt = 0; nt < 8; nt++) {
        const int c0 = nt*8 + q2;
        *reinterpret_cast<float2*>(g_A1B + (size_t)v0*64 + c0) = make_float2(D[nt*4+0], D[nt*4+1]);
        *reinterpret_cast<float2*>(g_A1B + (size_t)v1*64 + c0) = make_float2(D[nt*4+2], D[nt*4+3]);
    }
}

// ---------------------------------------------------------------------------
// k_main: int8 two-term pipeline. Block = 256 threads = 8 warps x 16 pairs.
// smem: [0..6144) int8 B-frags; [6144..7168) fp32 consts; then staging.
// ---------------------------------------------------------------------------
#define SM_CONST 6144
#define SM_STAGE_B (7168 * 4)
#define STAGE_PER_WARP 2560         // T1 (16 rows x 72B) + T2
#define DSM_BYTES (SM_STAGE_B + 8 * STAGE_PER_WARP)   // 49152 = 48KB

// quantize one row (16 values, nt-major pairs) into staging; returns sA = max/127
__device__ __forceinline__ float quant_row(const float* v, char* T1row, char* T2row, int q2)
{
    float m = 0.f;
    #pragma unroll
    for (int i = 0; i < 16; i++) m = fmaxf(m, v[i]);
    m = fmaxf(m, __shfl_xor_sync(0xffffffffu, m, 1));
    m = fmaxf(m, __shfl_xor_sync(0xffffffffu, m, 2));
    const float inv = (m > 0.f) ? 127.f/m : 0.f;
    #pragma unroll
    for (int nt = 0; nt < 8; nt++) {
        const float q0 = v[2*nt]   * inv;
        const float q1 = v[2*nt+1] * inv;
        const int i0 = __float2int_rn(q0);
        const int i1 = __float2int_rn(q1);
        const float r0 = fminf((q0 - (float)i0) * 256.f, 127.f);
        const float r1 = fminf((q1 - (float)i1) * 256.f, 127.f);
        const int j0 = __float2int_rn(r0);
        const int j1 = __float2int_rn(r1);
        *(u16*)(T1row + nt*8 + q2) = (u16)((i0 & 0xFF) | ((i1 & 0xFF) << 8));
        *(u16*)(T2row + nt*8 + q2) = (u16)((j0 & 0xFF) | ((j1 & 0xFF) << 8));
    }
    return m * (1.f/127.f);
}

__device__ __forceinline__ void load_afrags(const char* T, int g, int qb, u32* a)
{
    #pragma unroll
    for (int kt = 0; kt < 2; kt++) {
        a[kt*4+0] = *(const u32*)(T + (g  )*72 + kt*32 +      qb);
        a[kt*4+1] = *(const u32*)(T + (g+8)*72 + kt*32 +      qb);
        a[kt*4+2] = *(const u32*)(T + (g  )*72 + kt*32 + 16 + qb);
        a[kt*4+3] = *(const u32*)(T + (g+8)*72 + kt*32 + 16 + qb);
    }
}

__global__ void __launch_bounds__(256) k_main(
    const int*   __restrict__ nodes,
    const int*   __restrict__ nidx,
    const float* __restrict__ labels,
    const float* __restrict__ w1W,
    const float* __restrict__ w1b,
    const float* __restrict__ w2b,
    const float* __restrict__ a1b,
    const float* __restrict__ a2b,
    const float* __restrict__ a3W,
    const float* __restrict__ a3b)
{
    extern __shared__ u32 dsm[];
    u32*   sBFI = dsm;                          // 6144 u32
    float* sW1L = (float*)(dsm + SM_CONST);     // 512
    float* sB1  = sW1L + 512;                   // 64
    float* sB2  = sB1 + 64;
    float* sBa1 = sB2 + 64;
    float* sBa2 = sBa1 + 64;
    float* sA3  = sBa2 + 64;
    float* sCsc = sA3 + 64;                     // 192
    char*  stage = ((char*)dsm) + SM_STAGE_B;

    const int tid = threadIdx.x;
    {
        for (int i = tid; i < 6144; i += 256) sBFI[i] = g_WfI[i];
        for (int i = tid; i < 512;  i += 256) sW1L[i] = w1W[4096 + i];
        for (int i = tid; i < 192;  i += 256) sCsc[i] = g_Wsc[i];
        if (tid < 64) {
            sB1 [tid] = w1b[tid];
            sB2 [tid] = w2b[tid];
            sBa1[tid] = a1b[tid];
            sBa2[tid] = a2b[tid];
            sA3 [tid] = a3W[tid];
        }
    }
    __syncthreads();

    const float a3b0 = a3b[0];
    const int wid  = tid >> 5;
    const int lane = tid & 31;
    const int g    = lane >> 2;
    const int q2   = (lane & 3) << 1;
    const int qb   = (lane & 3) << 2;

    char* T1 = stage + wid * STAGE_PER_WARP;
    char* T2 = T1 + 1280;

    for (int t = blockIdx.x; t < NTILE; t += gridDim.x) {
        const int p0 = t*128 + wid*16 + g;       // row g
        const int p1 = p0 + 8;                   // row g+8

        float vA[16], vB[16];
        float sA0, sA1;

        // ================= LAYER 1 (scalar fp32) =================
        #pragma unroll
        for (int rr = 0; rr < 2; rr++) {
            const int p  = rr ? p1 : p0;
            float* v = rr ? vB : vA;
            const int ni = __ldg(&nidx[p]);
            const float* Pr = g_P + (size_t)ni * 64;
            const float4* lv = reinterpret_cast<const float4*>(labels + (size_t)p * 8);
            const float4 la = lv[0], lb = lv[1];
            const float lab[8] = { la.x, la.y, la.z, la.w, lb.x, lb.y, lb.z, lb.w };
            #pragma unroll
            for (int nt = 0; nt < 8; nt++) {
                const int c0 = nt*8 + q2;
                const float2 pa = *reinterpret_cast<const float2*>(Pr + c0);
                float v0 = pa.x + sB1[c0];
                float v1 = pa.y + sB1[c0+1];
                #pragma unroll
                for (int j = 0; j < 8; j++) {
                    const float* wr = sW1L + j*64 + c0;
                    v0 = fmaf(lab[j], wr[0], v0);
                    v1 = fmaf(lab[j], wr[1], v1);
                }
                v[2*nt]   = fmaxf(v0, 0.f);
                v[2*nt+1] = fmaxf(v1, 0.f);
            }
        }

        u32 a1r[8], a2r[8];

        // quantize h -> staging -> A frags
        sA0 = quant_row(vA, T1 + g*72,     T2 + g*72,     q2);
        sA1 = quant_row(vB, T1 + (g+8)*72, T2 + (g+8)*72, q2);
        __syncwarp();
        load_afrags(T1, g, qb, a1r);
        load_afrags(T2, g, qb, a2r);
        __syncwarp();

        // ============ LAYERS 2..4 via IMMA ============
        #pragma unroll 1
        for (int L = 0; L < 3; L++) {
            const u32* base = sBFI + L*2048;
            const float* bias = (L == 0) ? sB2 : (L == 1) ? sBa1 : sBa2;
            const float* csc  = sCsc + L*64;

            const float* G0 = 0; const float* G1 = 0;
            if (L == 1) {
                G0 = g_A1B + (size_t)__ldg(&nodes[p0 / K_N]) * 64;
                G1 = g_A1B + (size_t)__ldg(&nodes[p1 / K_N]) * 64;
            }

            float sc0 = 0.f, sc1 = 0.f;

            #pragma unroll
            for (int nt = 0; nt < 8; nt++) {
                int g11_0=0,g11_1=0,g11_2=0,g11_3=0;
                int g12_0=0,g12_1=0,g12_2=0,g12_3=0;
                #pragma unroll
                for (int kt = 0; kt < 2; kt++) {
                    const uint2 b1 = *reinterpret_cast<const uint2*>(base + (0*2+kt)*512 + nt*64 + lane*2);
                    const uint2 b2 = *reinterpret_cast<const uint2*>(base + (1*2+kt)*512 + nt*64 + lane*2);
                    imma16832(g11_0,g11_1,g11_2,g11_3, a1r[kt*4],a1r[kt*4+1],a1r[kt*4+2],a1r[kt*4+3], b1.x,b1.y);
                    imma16832(g12_0,g12_1,g12_2,g12_3, a1r[kt*4],a1r[kt*4+1],a1r[kt*4+2],a1r[kt*4+3], b2.x,b2.y);
                    imma16832(g12_0,g12_1,g12_2,g12_3, a2r[kt*4],a2r[kt*4+1],a2r[kt*4+2],a2r[kt*4+3], b1.x,b1.y);
                }
                const int c0 = nt*8 + q2;
                const float cs0 = csc[c0], cs1 = csc[c0+1];
                const float b0f = bias[c0], b1f = bias[c0+1];
                const float t0 = fmaf((float)g12_0, 0.00390625f, (float)g11_0);
                const float t1 = fmaf((float)g12_1, 0.00390625f, (float)g11_1);
                const float t2 = fmaf((float)g12_2, 0.00390625f, (float)g11_2);
                const float t3 = fmaf((float)g12_3, 0.00390625f, (float)g11_3);
                float v0 = fmaf(t0, sA0*cs0, b0f);
                float v1 = fmaf(t1, sA0*cs1, b1f);
                float v2 = fmaf(t2, sA1*cs0, b0f);
                float v3 = fmaf(t3, sA1*cs1, b1f);
                if (L == 1) {
                    const float2 gg0 = *reinterpret_cast<const float2*>(G0 + c0);
                    const float2 gg1 = *reinterpret_cast<const float2*>(G1 + c0);
                    v0 += gg0.x; v1 += gg0.y; v2 += gg1.x; v3 += gg1.y;
                }
                v0 = fmaxf(v0, 0.f); v1 = fmaxf(v1, 0.f);
                v2 = fmaxf(v2, 0.f); v3 = fmaxf(v3, 0.f);

                if (L == 2) {
                    const float w0 = sA3[c0], w1 = sA3[c0+1];
                    sc0 = fmaf(v0, w0, fmaf(v1, w1, sc0));
                    sc1 = fmaf(v2, w0, fmaf(v3, w1, sc1));
                } else {
                    if (L == 0) {
                        *reinterpret_cast<float2*>(g_O + (size_t)p0*64 + c0) = make_float2(v0, v1);
                        *reinterpret_cast<float2*>(g_O + (size_t)p1*64 + c0) = make_float2(v2, v3);
                    }
                    vA[2*nt] = v0; vA[2*nt+1] = v1;
                    vB[2*nt] = v2; vB[2*nt+1] = v3;
                }
            }

            if (L == 2) {
                sc0 += __shfl_xor_sync(0xffffffffu, sc0, 1);
                sc0 += __shfl_xor_sync(0xffffffffu, sc0, 2);
                sc1 += __shfl_xor_sync(0xffffffffu, sc1, 1);
                sc1 += __shfl_xor_sync(0xffffffffu, sc1, 2);
                if ((lane & 3) == 0) {
                    g_S[p0] = sc0 + a3b0;
                    g_S[p1] = sc1 + a3b0;
                }
            } else {
                __syncwarp();
                sA0 = quant_row(vA, T1 + g*72,     T2 + g*72,     q2);
                sA1 = quant_row(vB, T1 + (g+8)*72, T2 + (g+8)*72, q2);
                __syncwarp();
                load_afrags(T1, g, qb, a1r);
                load_afrags(T2, g, qb, a2r);
                __syncwarp();
            }
        }
    }
}

// ---------------------------------------------------------------------------
// k_agg: masked softmax + weighted aggregate. float4 dual-row loads.
// ---------------------------------------------------------------------------
__global__ void __launch_bounds__(256) k_agg(const int*   __restrict__ nodes,
                                             const int*   __restrict__ nlen,
                                             const float* __restrict__ u2e,
                                             float*       __restrict__ out)
{
    const int wid  = (blockIdx.x * 256 + threadIdx.x) >> 5;
    const int lane = threadIdx.x & 31;
    if (wid >= B_N) return;
    const int b   = wid;
    const int len = nlen[b];

    if (len <= 0) {
        const int node = nodes[b];
        const float2* src = reinterpret_cast<const float2*>(u2e + (size_t)node * 64);
        reinterpret_cast<float2*>(out + (size_t)b * 64)[lane] = src[lane];
        return;
    }

    const float* Sb = g_S + (size_t)b * K_N;
    float s0 = (lane      < len) ? Sb[lane]      : -3.0e38f;
    float s1 = (lane + 32 < len) ? Sb[lane + 32] : -3.0e38f;

    float m = fmaxf(s0, s1);
    #pragma unroll
    for (int o = 16; o > 0; o >>= 1) m = fmaxf(m, __shfl_xor_sync(0xffffffffu, m, o));

    const float e0 = (lane      < len) ? expf(s0 - m) : 0.f;
    const float e1 = (lane + 32 < len) ? expf(s1 - m) : 0.f;

    float ss = e0 + e1;
    #pragma unroll
    for (int o = 16; o > 0; o >>= 1) ss += __shfl_xor_sync(0xffffffffu, ss, o);

    const float inv = 1.f / ss;
    const float w0 = e0 * inv;
    const float w1 = e1 * inv;

    // dual-row float4: lane = half*16 + col4
    const int half = lane >> 4;
    const int col4 = lane & 15;
    float4 agg = make_float4(0.f, 0.f, 0.f, 0.f);
    const float* Ob = g_O + (size_t)b * K_N * 64;
    for (int k = 0; k < len; k += 2) {
        const int row = k + half;
        const float awA = __shfl_sync(0xffffffffu, w0, row & 31);
        const float awB = __shfl_sync(0xffffffffu, w1, row & 31);
        const float aw  = (row < 32) ? awA : awB;   // rows >= len have weight 0
        const float4 ov = *reinterpret_cast<const float4*>(Ob + row*64 + col4*4);
        agg.x = fmaf(aw, ov.x, agg.x);
        agg.y = fmaf(aw, ov.y, agg.y);
        agg.z = fmaf(aw, ov.z, agg.z);
        agg.w = fmaf(aw, ov.w, agg.w);
    }
    agg.x += __shfl_xor_sync(0xffffffffu, agg.x, 16);
    agg.y += __shfl_xor_sync(0xffffffffu, agg.y, 16);
    agg.z += __shfl_xor_sync(0xffffffffu, agg.z, 16);
    agg.w += __shfl_xor_sync(0xffffffffu, agg.w, 16);
    if (lane < 16)
        *reinterpret_cast<float4*>(out + (size_t)b * 64 + col4*4) = agg;
}

// ---------------------------------------------------------------------------
// kernel_launch
// ---------------------------------------------------------------------------
extern "C" void kernel_launch(void* const* d_in, const int* in_sizes, int n_in,
                              void* d_out, int out_size)
{
    const int*   nodes  = (const int*)  d_in[0];
    const int*   nidx   = (const int*)  d_in[1];
    const int*   nlen   = (const int*)  d_in[2];
    const float* labels = (const float*)d_in[3];
    const float* u2e    = (const float*)d_in[4];
    const float* w1W    = (const float*)d_in[5];
    const float* w1b    = (const float*)d_in[6];
    const float* w2W    = (const float*)d_in[7];
    const float* w2b    = (const float*)d_in[8];
    const float* a1W    = (const float*)d_in[9];
    const float* a1b    = (const float*)d_in[10];
    const float* a2W    = (const float*)d_in[11];
    const float* a2b    = (const float*)d_in[12];
    const float* a3W    = (const float*)d_in[13];
    const float* a3b    = (const float*)d_in[14];
    float* out = (float*)d_out;

    cudaFuncSetAttribute(k_main, cudaFuncAttributeMaxDynamicSharedMemorySize, DSM_BYTES);

    k_wfragB<<<8, 256>>>(w1W, a1W);
    k_wfragI<<<3, 64>>>(w2W, a1W, a2W);
    k_pre   <<<(VTILE + 7) / 8, 256>>>(u2e);
    k_main  <<<296, 256, DSM_BYTES>>>(nodes, nidx, labels, w1W, w1b,
                                      w2b, a1b, a2b, a3W, a3b);
    k_agg   <<<(B_N * 32 + 255) / 256, 256>>>(nodes, nlen, u2e, out);
}

// round 9
// speedup vs baseline: 2.6111x; 2.6111x over previous
#include <cuda_runtime.h>
#include <cuda_fp16.h>
#include <cstdint>
#include <math.h>

#define B_N   16384
#define K_N   50
#define V_N   100000
#define BK_N  (B_N * K_N)          // 819200
#define NTILE (BK_N / 128)         // 6400 tiles of 128 pairs
#define VTILE (V_N / 16)           // 6250 vocab warp-tiles

typedef unsigned int u32;

// ---------------------------------------------------------------------------
// Device scratch (static — no cudaMalloc allowed)
// ---------------------------------------------------------------------------
__device__ float g_P  [(size_t)V_N * 64];      // u2e @ w1_W[0:64,:]
__device__ float g_A1B[(size_t)V_N * 64];      // u2e @ a1_W[64:128,:]
__device__ float g_O  [(size_t)BK_N * 64];     // o_history (fp32)
__device__ float g_S  [(size_t)BK_N];          // attention scores
// fp16 B fragments: [L:5][kt:4][nt:8][lane:32][reg:2] u32 (fp16x2)
// L: 0=w2W  1=a1W[0:64]  2=a2W  3=w1W[0:64]  4=a1W[64:128]
__device__ u32   g_Wf [5 * 2048];              // 40KB

// ---------------------------------------------------------------------------
// fp16 helpers
// ---------------------------------------------------------------------------
__device__ __forceinline__ u32 pack_h2(float v0, float v1) {
    __half2 h = __floats2half2_rn(v0, v1);
    return *reinterpret_cast<u32*>(&h);
}
// Split two f32 into fp16x2 hi + fp16x2 residual (exact to ~2^-22).
__device__ __forceinline__ void split2h(float v0, float v1, u32& h, u32& l) {
    const __half2 hh = __floats2half2_rn(v0, v1);
    h = *reinterpret_cast<const u32*>(&hh);
    const float2 hf = __half22float2(hh);
    const __half2 ll = __floats2half2_rn(v0 - hf.x, v1 - hf.y);
    l = *reinterpret_cast<const u32*>(&ll);
}
// m16n8k16 row.col fp16 MMA, fp32 accumulate (sm_80+ baseline)
__device__ __forceinline__ void mma16816(float& d0, float& d1, float& d2, float& d3,
                                         u32 a0, u32 a1, u32 a2, u32 a3,
                                         u32 b0, u32 b1) {
    asm("mma.sync.aligned.m16n8k16.row.col.f32.f16.f16.f32 "
        "{%0,%1,%2,%3}, {%4,%5,%6,%7}, {%8,%9}, {%0,%1,%2,%3};"
        : "+f"(d0), "+f"(d1), "+f"(d2), "+f"(d3)
        : "r"(a0), "r"(a1), "r"(a2), "r"(a3), "r"(b0), "r"(b1));
}

// ---------------------------------------------------------------------------
// Kernel 0: fp16 B-fragments, 5 matrices (single hi term per weight).
// B fragment (m16n8k16 row.col): n = nt*8+lane/4, k0 = kt*16+(lane%4)*2
//   reg0 = {W[k0][n], W[k0+1][n]}, reg1 = {W[k0+8][n], W[k0+9][n]}
// ---------------------------------------------------------------------------
__global__ void __launch_bounds__(256) k_wfrag(const float* __restrict__ w2W,
                                               const float* __restrict__ a1W,
                                               const float* __restrict__ a2W,
                                               const float* __restrict__ w1W)
{
    const int idx = blockIdx.x * 256 + threadIdx.x;   // 5*4*8*32 = 5120
    if (idx >= 5120) return;
    const int lane = idx & 31;
    const int nt   = (idx >> 5) & 7;
    const int kt   = (idx >> 8) & 3;
    const int L    = idx >> 10;

    const float* W;
    if (L == 0)      W = w2W;
    else if (L == 1) W = a1W;
    else if (L == 2) W = a2W;
    else if (L == 3) W = w1W;
    else             W = a1W + 4096;    // rows 64..127

    const int n  = nt * 8 + (lane >> 2);
    const int k0 = kt * 16 + (lane & 3) * 2;

    const int f = L * 2048 + ((kt*8 + nt)*32 + lane)*2;
    g_Wf[f]     = pack_h2(W[k0*64+n],     W[(k0+1)*64+n]);
    g_Wf[f + 1] = pack_h2(W[(k0+8)*64+n], W[(k0+9)*64+n]);
}

// ---------------------------------------------------------------------------
// Single-tile 64->64 GEMM (M=16): 2-term fp16 split (A hi/lo, W hi only).
// ---------------------------------------------------------------------------
__device__ __forceinline__ void gemm64(float* D, const u32* ah, const u32* al,
                                       const u32* sBFL, int lane)
{
    #pragma unroll
    for (int nt = 0; nt < 8; nt++) {
        float d0=0.f,d1=0.f,d2=0.f,d3=0.f;
        #pragma unroll
        for (int kt = 0; kt < 4; kt++) {
            const uint2 b = *reinterpret_cast<const uint2*>(sBFL + (kt*8 + nt)*64 + lane*2);
            mma16816(d0,d1,d2,d3, ah[kt*4],ah[kt*4+1],ah[kt*4+2],ah[kt*4+3], b.x,b.y);
            mma16816(d0,d1,d2,d3, al[kt*4],al[kt*4+1],al[kt*4+2],al[kt*4+3], b.x,b.y);
        }
        D[nt*4+0]=d0; D[nt*4+1]=d1; D[nt*4+2]=d2; D[nt*4+3]=d3;
    }
}

// Dual-tile (M=32): two A tiles share each B-fragment load.
__device__ __forceinline__ void gemm64x2(float* D,
                                         const u32* ahA, const u32* alA,
                                         const u32* ahB, const u32* alB,
                                         const u32* sBFL, int lane)
{
    #pragma unroll
    for (int nt = 0; nt < 8; nt++) {
        float d0=0.f,d1=0.f,d2=0.f,d3=0.f,d4=0.f,d5=0.f,d6=0.f,d7=0.f;
        #pragma unroll
        for (int kt = 0; kt < 4; kt++) {
            const uint2 b = *reinterpret_cast<const uint2*>(sBFL + (kt*8 + nt)*64 + lane*2);
            mma16816(d0,d1,d2,d3, ahA[kt*4],ahA[kt*4+1],ahA[kt*4+2],ahA[kt*4+3], b.x,b.y);
            mma16816(d0,d1,d2,d3, alA[kt*4],alA[kt*4+1],alA[kt*4+2],alA[kt*4+3], b.x,b.y);
            mma16816(d4,d5,d6,d7, ahB[kt*4],ahB[kt*4+1],ahB[kt*4+2],ahB[kt*4+3], b.x,b.y);
            mma16816(d4,d5,d6,d7, alB[kt*4],alB[kt*4+1],alB[kt*4+2],alB[kt*4+3], b.x,b.y);
        }
        D[nt*8+0]=d0; D[nt*8+1]=d1; D[nt*8+2]=d2; D[nt*8+3]=d3;
        D[nt*8+4]=d4; D[nt*8+5]=d5; D[nt*8+6]=d6; D[nt*8+7]=d7;
    }
}

// ---------------------------------------------------------------------------
// Kernel 1: HMMA per-vocab precompute of P and A1B.
// ---------------------------------------------------------------------------
__global__ void __launch_bounds__(256) k_pre(const float* __restrict__ u2e)
{
    __shared__ u32 sBF[4096];        // L=3 (W1) and L=4 frag blocks, 16KB

    const int tid = threadIdx.x;
    {
        const uint4* src = reinterpret_cast<const uint4*>(g_Wf + 3 * 2048);
        uint4* dst = reinterpret_cast<uint4*>(sBF);
        for (int i = tid; i < 1024; i += 256) dst[i] = src[i];
    }
    __syncthreads();

    const int wid  = tid >> 5;
    const int lane = tid & 31;
    const int g    = lane >> 2;
    const int q2   = (lane & 3) << 1;

    const int wt = blockIdx.x * 8 + wid;
    if (wt >= VTILE) return;
    const int v0 = wt * 16 + g;
    const int v1 = v0 + 8;

    u32 ah[16], al[16];
    #pragma unroll
    for (int rr = 0; rr < 2; rr++) {
        const float* Mr = u2e + (size_t)(wt*16 + g + rr*8) * 64;
        #pragma unroll
        for (int kt = 0; kt < 4; kt++) {
            const int c0 = kt*16 + q2;
            const float2 pa = *reinterpret_cast<const float2*>(Mr + c0);
            const float2 pb = *reinterpret_cast<const float2*>(Mr + c0 + 8);
            split2h(pa.x, pa.y, ah[kt*4 + rr],     al[kt*4 + rr]);
            split2h(pb.x, pb.y, ah[kt*4 + 2 + rr], al[kt*4 + 2 + rr]);
        }
    }

    float D[32];
    gemm64(D, ah, al, sBF, lane);
    #pragma unroll
    for (int nt = 0; nt < 8; nt++) {
        const int c0 = nt*8 + q2;
        *reinterpret_cast<float2*>(g_P + (size_t)v0*64 + c0) = make_float2(D[nt*4+0], D[nt*4+1]);
        *reinterpret_cast<float2*>(g_P + (size_t)v1*64 + c0) = make_float2(D[nt*4+2], D[nt*4+3]);
    }
    gemm64(D, ah, al, sBF + 2048, lane);
    #pragma unroll
    for (int nt = 0; nt < 8; nt++) {
        const int c0 = nt*8 + q2;
        *reinterpret_cast<float2*>(g_A1B + (size_t)v0*64 + c0) = make_float2(D[nt*4+0], D[nt*4+1]);
        *reinterpret_cast<float2*>(g_A1B + (size_t)v1*64 + c0) = make_float2(D[nt*4+2], D[nt*4+3]);
    }
}

// ---------------------------------------------------------------------------
// Main kernel: layers 1..4 + scores. Each warp: 32 pairs (two m16 tiles).
// Block = 4 warps = 128 pairs.
// ---------------------------------------------------------------------------
#define DSM_U32  (6144 + 512 + 5*64)   // 6976 u32 = 27904 B
#define DSM_BYTES (DSM_U32 * 4)

__global__ void __launch_bounds__(128, 2) k_main(
    const int*   __restrict__ nodes,
    const int*   __restrict__ nidx,
    const float* __restrict__ labels,
    const float* __restrict__ w1W,
    const float* __restrict__ w1b,
    const float* __restrict__ w2b,
    const float* __restrict__ a1b,
    const float* __restrict__ a2b,
    const float* __restrict__ a3W,
    const float* __restrict__ a3b)
{
    extern __shared__ u32 dsm[];
    u32*   sBF  = dsm;                       // 6144 u32 (24KB): L=0,1,2
    float* sW1L = (float*)(dsm + 6144);      // 512
    float* sB1  = sW1L + 512;
    float* sB2  = sB1 + 64;
    float* sBa1 = sB2 + 64;
    float* sBa2 = sBa1 + 64;
    float* sA3  = sBa2 + 64;

    const int tid = threadIdx.x;
    {
        const uint4* src = reinterpret_cast<const uint4*>(g_Wf);
        uint4* dst = reinterpret_cast<uint4*>(sBF);
        for (int i = tid; i < 1536; i += 128) dst[i] = src[i];
        for (int i = tid; i < 512; i += 128) sW1L[i] = w1W[4096 + i];
        if (tid < 64) {
            sB1 [tid] = w1b[tid];
            sB2 [tid] = w2b[tid];
            sBa1[tid] = a1b[tid];
            sBa2[tid] = a2b[tid];
            sA3 [tid] = a3W[tid];
        }
    }
    __syncthreads();

    const float a3b0 = a3b[0];
    const int wid  = tid >> 5;             // 0..3
    const int lane = tid & 31;
    const int g    = lane >> 2;            // 0..7  (row within m16 tile)
    const int q2   = (lane & 3) << 1;      // 0,2,4,6 (col pair base)

    for (int t = blockIdx.x; t < NTILE; t += gridDim.x) {
        const int pb = t * 128 + wid * 32 + g;   // rows pb, pb+8, pb+16, pb+24

        u32 ahA[16], alA[16], ahB[16], alB[16];

        // ================= LAYER 1 (scalar) → A fragments =================
        #pragma unroll
        for (int rr = 0; rr < 4; rr++) {
            const int p  = pb + rr * 8;
            u32* ah = (rr < 2) ? ahA : ahB;
            u32* al = (rr < 2) ? alA : alB;
            const int sl = rr & 1;

            const int ni = __ldg(&nidx[p]);
            const float* Pr = g_P + (size_t)ni * 64;
            const float4* lv = reinterpret_cast<const float4*>(labels + (size_t)p * 8);
            const float4 la = lv[0], lb = lv[1];
            const float lab[8] = { la.x, la.y, la.z, la.w, lb.x, lb.y, lb.z, lb.w };

            #pragma unroll
            for (int kt = 0; kt < 4; kt++) {
                const int c0 = kt * 16 + q2;
                const float2 pa = *reinterpret_cast<const float2*>(Pr + c0);
                const float2 pbv = *reinterpret_cast<const float2*>(Pr + c0 + 8);
                float v0 = pa.x + sB1[c0];
                float v1 = pa.y + sB1[c0 + 1];
                float v2 = pbv.x + sB1[c0 + 8];
                float v3 = pbv.y + sB1[c0 + 9];
                #pragma unroll
                for (int j = 0; j < 8; j++) {
                    const float* wr = sW1L + j * 64 + c0;
                    v0 = fmaf(lab[j], wr[0], v0);
                    v1 = fmaf(lab[j], wr[1], v1);
                    v2 = fmaf(lab[j], wr[8], v2);
                    v3 = fmaf(lab[j], wr[9], v3);
                }
                v0 = fmaxf(v0, 0.f); v1 = fmaxf(v1, 0.f);
                v2 = fmaxf(v2, 0.f); v3 = fmaxf(v3, 0.f);
                split2h(v0, v1, ah[kt*4 + sl],     al[kt*4 + sl]);
                split2h(v2, v3, ah[kt*4 + 2 + sl], al[kt*4 + 2 + sl]);
            }
        }

        float D[64];

        // ================= LAYER 2: o = relu(h @ W2 + b2) =================
        gemm64x2(D, ahA, alA, ahB, alB, sBF, lane);
        #pragma unroll
        for (int nt = 0; nt < 8; nt++) {
            const int c0 = nt * 8 + q2;
            const int kt = nt >> 1, hf = nt & 1;
            #pragma unroll
            for (int half = 0; half < 2; half++) {
                const float b0 = sB2[c0], b1 = sB2[c0 + 1];
                const float v0 = fmaxf(D[nt*8 + half*4 + 0] + b0, 0.f);
                const float v1 = fmaxf(D[nt*8 + half*4 + 1] + b1, 0.f);
                const float v2 = fmaxf(D[nt*8 + half*4 + 2] + b0, 0.f);
                const float v3 = fmaxf(D[nt*8 + half*4 + 3] + b1, 0.f);
                const int r0 = pb + half * 16;
                *reinterpret_cast<float2*>(g_O + (size_t)r0 * 64 + c0)       = make_float2(v0, v1);
                *reinterpret_cast<float2*>(g_O + (size_t)(r0 + 8) * 64 + c0) = make_float2(v2, v3);
                u32* ah = half ? ahB : ahA;
                u32* al = half ? alB : alA;
                split2h(v0, v1, ah[kt*4 + hf*2 + 0], al[kt*4 + hf*2 + 0]);
                split2h(v2, v3, ah[kt*4 + hf*2 + 1], al[kt*4 + hf*2 + 1]);
            }
        }

        // ============ LAYER 3: a = relu(o @ A1a + A1B[node] + b) ==========
        const float* G[4];
        #pragma unroll
        for (int rr = 0; rr < 4; rr++)
            G[rr] = g_A1B + (size_t)__ldg(&nodes[(pb + rr * 8) / K_N]) * 64;

        gemm64x2(D, ahA, alA, ahB, alB, sBF + 2048, lane);
        #pragma unroll
        for (int nt = 0; nt < 8; nt++) {
            const int c0 = nt * 8 + q2;
            const int kt = nt >> 1, hf = nt & 1;
            #pragma unroll
            for (int half = 0; half < 2; half++) {
                const float2 g0 = *reinterpret_cast<const float2*>(G[half*2]     + c0);
                const float2 g1 = *reinterpret_cast<const float2*>(G[half*2 + 1] + c0);
                const float b0 = sBa1[c0], b1 = sBa1[c0 + 1];
                const float v0 = fmaxf(D[nt*8 + half*4 + 0] + b0 + g0.x, 0.f);
                const float v1 = fmaxf(D[nt*8 + half*4 + 1] + b1 + g0.y, 0.f);
                const float v2 = fmaxf(D[nt*8 + half*4 + 2] + b0 + g1.x, 0.f);
                const float v3 = fmaxf(D[nt*8 + half*4 + 3] + b1 + g1.y, 0.f);
                u32* ah = half ? ahB : ahA;
                u32* al = half ? alB : alA;
                split2h(v0, v1, ah[kt*4 + hf*2 + 0], al[kt*4 + hf*2 + 0]);
                split2h(v2, v3, ah[kt*4 + hf*2 + 1], al[kt*4 + hf*2 + 1]);
            }
        }

        // ========= LAYER 4: a2 = relu(a @ A2 + b); score = a2 . a3 ========
        gemm64x2(D, ahA, alA, ahB, alB, sBF + 4096, lane);
        float s[4] = {0.f, 0.f, 0.f, 0.f};
        #pragma unroll
        for (int nt = 0; nt < 8; nt++) {
            const int c0 = nt * 8 + q2;
            const float b0 = sBa2[c0], b1 = sBa2[c0 + 1];
            const float w0 = sA3[c0],  w1 = sA3[c0 + 1];
            #pragma unroll
            for (int half = 0; half < 2; half++) {
                const float v0 = fmaxf(D[nt*8 + half*4 + 0] + b0, 0.f);
                const float v1 = fmaxf(D[nt*8 + half*4 + 1] + b1, 0.f);
                const float v2 = fmaxf(D[nt*8 + half*4 + 2] + b0, 0.f);
                const float v3 = fmaxf(D[nt*8 + half*4 + 3] + b1, 0.f);
                s[half*2]     = fmaf(v0, w0, fmaf(v1, w1, s[half*2]));
                s[half*2 + 1] = fmaf(v2, w0, fmaf(v3, w1, s[half*2 + 1]));
            }
        }
        #pragma unroll
        for (int rr = 0; rr < 4; rr++) {
            float sv = s[rr];
            sv += __shfl_xor_sync(0xffffffffu, sv, 1);
            sv += __shfl_xor_sync(0xffffffffu, sv, 2);
            if ((lane & 3) == 0) g_S[pb + rr * 8] = sv + a3b0;
        }
    }
}

// ---------------------------------------------------------------------------
// Kernel 3: masked softmax over K neighbors + weighted aggregate (R7 proven)
// ---------------------------------------------------------------------------
__global__ void __launch_bounds__(256) k_agg(const int*   __restrict__ nodes,
                                             const int*   __restrict__ nlen,
                                             const float* __restrict__ u2e,
                                             float*       __restrict__ out)
{
    const int wid  = (blockIdx.x * 256 + threadIdx.x) >> 5;
    const int lane = threadIdx.x & 31;
    if (wid >= B_N) return;
    const int b   = wid;
    const int len = nlen[b];

    if (len <= 0) {
        const int node = nodes[b];
        const float2* src = reinterpret_cast<const float2*>(u2e + (size_t)node * 64);
        reinterpret_cast<float2*>(out + (size_t)b * 64)[lane] = src[lane];
        return;
    }

    const float* Sb = g_S + (size_t)b * K_N;
    float s0 = (lane      < len) ? Sb[lane]      : -3.0e38f;
    float s1 = (lane + 32 < len) ? Sb[lane + 32] : -3.0e38f;

    float m = fmaxf(s0, s1);
    #pragma unroll
    for (int o = 16; o > 0; o >>= 1) m = fmaxf(m, __shfl_xor_sync(0xffffffffu, m, o));

    const float e0 = (lane      < len) ? expf(s0 - m) : 0.f;
    const float e1 = (lane + 32 < len) ? expf(s1 - m) : 0.f;

    float ss = e0 + e1;
    #pragma unroll
    for (int o = 16; o > 0; o >>= 1) ss += __shfl_xor_sync(0xffffffffu, ss, o);

    const float inv = 1.f / ss;
    const float w0 = e0 * inv;
    const float w1 = e1 * inv;

    float2 agg = make_float2(0.f, 0.f);
    const float2* Ob = reinterpret_cast<const float2*>(g_O + (size_t)b * K_N * 64);
    for (int k = 0; k < len; k++) {
        const float ak = (k < 32) ? __shfl_sync(0xffffffffu, w0, k)
                                  : __shfl_sync(0xffffffffu, w1, k - 32);
        const float2 ov = Ob[k * 32 + lane];
        agg.x = fmaf(ak, ov.x, agg.x);
        agg.y = fmaf(ak, ov.y, agg.y);
    }
    reinterpret_cast<float2*>(out + (size_t)b * 64)[lane] = agg;
}

// ---------------------------------------------------------------------------
// kernel_launch
// ---------------------------------------------------------------------------
extern "C" void kernel_launch(void* const* d_in, const int* in_sizes, int n_in,
                              void* d_out, int out_size)
{
    const int*   nodes  = (const int*)  d_in[0];
    const int*   nidx   = (const int*)  d_in[1];
    const int*   nlen   = (const int*)  d_in[2];
    const float* labels = (const float*)d_in[3];
    const float* u2e    = (const float*)d_in[4];
    const float* w1W    = (const float*)d_in[5];
    const float* w1b    = (const float*)d_in[6];
    const float* w2W    = (const float*)d_in[7];
    const float* w2b    = (const float*)d_in[8];
    const float* a1W    = (const float*)d_in[9];
    const float* a1b    = (const float*)d_in[10];
    const float* a2W    = (const float*)d_in[11];
    const float* a2b    = (const float*)d_in[12];
    const float* a3W    = (const float*)d_in[13];
    const float* a3b    = (const float*)d_in[14];
    float* out = (float*)d_out;

    cudaFuncSetAttribute(k_main, cudaFuncAttributeMaxDynamicSharedMemorySize, DSM_BYTES);

    k_wfrag<<<20, 256>>>(w2W, a1W, a2W, w1W);
    k_pre  <<<(VTILE + 7) / 8, 256>>>(u2e);
    k_main <<<296, 128, DSM_BYTES>>>(nodes, nidx, labels, w1W, w1b,
                                     w2b, a1b, a2b, a3W, a3b);
    k_agg  <<<(B_N * 32 + 255) / 256, 256>>>(nodes, nlen, u2e, out);
}

// round 10
// speedup vs baseline: 2.9103x; 1.1146x over previous
#include <cuda_runtime.h>
#include <cuda_fp16.h>
#include <cstdint>
#include <math.h>

#define B_N   16384
#define K_N   50
#define V_N   100000
#define BK_N  (B_N * K_N)          // 819200
#define NTILE (BK_N / 128)         // 6400 tiles of 128 pairs
#define VTILE (V_N / 16)           // 6250 vocab warp-tiles

typedef unsigned int u32;

// ---------------------------------------------------------------------------
// Device scratch (static — no cudaMalloc allowed)
// ---------------------------------------------------------------------------
__device__ float g_P  [(size_t)V_N * 64];      // u2e @ w1_W[0:64,:]
__device__ float g_A1B[(size_t)V_N * 64];      // u2e @ a1_W[64:128,:]
__device__ float g_O  [(size_t)BK_N * 64];     // o_history (fp32)
__device__ float g_S  [(size_t)BK_N];          // attention scores
// fp16 B fragments: [L:5][kt:4][nt:8][lane:32][reg:2] u32 (fp16x2)
// L: 0=w2W  1=a1W[0:64]  2=a2W  3=w1W[0:64]  4=a1W[64:128]
__device__ u32   g_Wf [5 * 2048];              // 40KB

// ---------------------------------------------------------------------------
// fp16 helpers
// ---------------------------------------------------------------------------
__device__ __forceinline__ u32 pack_h2(float v0, float v1) {
    __half2 h = __floats2half2_rn(v0, v1);
    return *reinterpret_cast<u32*>(&h);
}
// Split two f32 into fp16x2 hi + fp16x2 residual (exact to ~2^-22).
__device__ __forceinline__ void split2h(float v0, float v1, u32& h, u32& l) {
    const __half2 hh = __floats2half2_rn(v0, v1);
    h = *reinterpret_cast<const u32*>(&hh);
    const float2 hf = __half22float2(hh);
    const __half2 ll = __floats2half2_rn(v0 - hf.x, v1 - hf.y);
    l = *reinterpret_cast<const u32*>(&ll);
}
// m16n8k16 row.col fp16 MMA, fp32 accumulate (sm_80+ baseline)
__device__ __forceinline__ void mma16816(float& d0, float& d1, float& d2, float& d3,
                                         u32 a0, u32 a1, u32 a2, u32 a3,
                                         u32 b0, u32 b1) {
    asm("mma.sync.aligned.m16n8k16.row.col.f32.f16.f16.f32 "
        "{%0,%1,%2,%3}, {%4,%5,%6,%7}, {%8,%9}, {%0,%1,%2,%3};"
        : "+f"(d0), "+f"(d1), "+f"(d2), "+f"(d3)
        : "r"(a0), "r"(a1), "r"(a2), "r"(a3), "r"(b0), "r"(b1));
}

// ---------------------------------------------------------------------------
// Kernel 0: fp16 B-fragments, 5 matrices (single hi term per weight).
// ---------------------------------------------------------------------------
__global__ void __launch_bounds__(256) k_wfrag(const float* __restrict__ w2W,
                                               const float* __restrict__ a1W,
                                               const float* __restrict__ a2W,
                                               const float* __restrict__ w1W)
{
    const int idx = blockIdx.x * 256 + threadIdx.x;   // 5*4*8*32 = 5120
    if (idx >= 5120) return;
    const int lane = idx & 31;
    const int nt   = (idx >> 5) & 7;
    const int kt   = (idx >> 8) & 3;
    const int L    = idx >> 10;

    const float* W;
    if (L == 0)      W = w2W;
    else if (L == 1) W = a1W;
    else if (L == 2) W = a2W;
    else if (L == 3) W = w1W;
    else             W = a1W + 4096;    // rows 64..127

    const int n  = nt * 8 + (lane >> 2);
    const int k0 = kt * 16 + (lane & 3) * 2;

    const int f = L * 2048 + ((kt*8 + nt)*32 + lane)*2;
    g_Wf[f]     = pack_h2(W[k0*64+n],     W[(k0+1)*64+n]);
    g_Wf[f + 1] = pack_h2(W[(k0+8)*64+n], W[(k0+9)*64+n]);
}

// ---------------------------------------------------------------------------
// Single-tile 64->64 GEMM (M=16): 2-term fp16 split (A hi/lo).
// ---------------------------------------------------------------------------
__device__ __forceinline__ void gemm64(float* D, const u32* ah, const u32* al,
                                       const u32* sBFL, int lane)
{
    #pragma unroll
    for (int nt = 0; nt < 8; nt++) {
        float d0=0.f,d1=0.f,d2=0.f,d3=0.f;
        #pragma unroll
        for (int kt = 0; kt < 4; kt++) {
            const uint2 b = *reinterpret_cast<const uint2*>(sBFL + (kt*8 + nt)*64 + lane*2);
            mma16816(d0,d1,d2,d3, ah[kt*4],ah[kt*4+1],ah[kt*4+2],ah[kt*4+3], b.x,b.y);
            mma16816(d0,d1,d2,d3, al[kt*4],al[kt*4+1],al[kt*4+2],al[kt*4+3], b.x,b.y);
        }
        D[nt*4+0]=d0; D[nt*4+1]=d1; D[nt*4+2]=d2; D[nt*4+3]=d3;
    }
}

// Dual-tile (M=32), 2-term A split: layer 2 (protects o accuracy).
__device__ __forceinline__ void gemm64x2(float* D,
                                         const u32* ahA, const u32* alA,
                                         const u32* ahB, const u32* alB,
                                         const u32* sBFL, int lane)
{
    #pragma unroll
    for (int nt = 0; nt < 8; nt++) {
        float d0=0.f,d1=0.f,d2=0.f,d3=0.f,d4=0.f,d5=0.f,d6=0.f,d7=0.f;
        #pragma unroll
        for (int kt = 0; kt < 4; kt++) {
            const uint2 b = *reinterpret_cast<const uint2*>(sBFL + (kt*8 + nt)*64 + lane*2);
            mma16816(d0,d1,d2,d3, ahA[kt*4],ahA[kt*4+1],ahA[kt*4+2],ahA[kt*4+3], b.x,b.y);
            mma16816(d0,d1,d2,d3, alA[kt*4],alA[kt*4+1],alA[kt*4+2],alA[kt*4+3], b.x,b.y);
            mma16816(d4,d5,d6,d7, ahB[kt*4],ahB[kt*4+1],ahB[kt*4+2],ahB[kt*4+3], b.x,b.y);
            mma16816(d4,d5,d6,d7, alB[kt*4],alB[kt*4+1],alB[kt*4+2],alB[kt*4+3], b.x,b.y);
        }
        D[nt*8+0]=d0; D[nt*8+1]=d1; D[nt*8+2]=d2; D[nt*8+3]=d3;
        D[nt*8+4]=d4; D[nt*8+5]=d5; D[nt*8+6]=d6; D[nt*8+7]=d7;
    }
}

// Dual-tile (M=32), single-term A: layers 3-4 (affect scores only).
__device__ __forceinline__ void gemm64x2_1t(float* D,
                                            const u32* ahA, const u32* ahB,
                                            const u32* sBFL, int lane)
{
    #pragma unroll
    for (int nt = 0; nt < 8; nt++) {
        float d0=0.f,d1=0.f,d2=0.f,d3=0.f,d4=0.f,d5=0.f,d6=0.f,d7=0.f;
        #pragma unroll
        for (int kt = 0; kt < 4; kt++) {
            const uint2 b = *reinterpret_cast<const uint2*>(sBFL + (kt*8 + nt)*64 + lane*2);
            mma16816(d0,d1,d2,d3, ahA[kt*4],ahA[kt*4+1],ahA[kt*4+2],ahA[kt*4+3], b.x,b.y);
            mma16816(d4,d5,d6,d7, ahB[kt*4],ahB[kt*4+1],ahB[kt*4+2],ahB[kt*4+3], b.x,b.y);
        }
        D[nt*8+0]=d0; D[nt*8+1]=d1; D[nt*8+2]=d2; D[nt*8+3]=d3;
        D[nt*8+4]=d4; D[nt*8+5]=d5; D[nt*8+6]=d6; D[nt*8+7]=d7;
    }
}

// ---------------------------------------------------------------------------
// Kernel 1: HMMA per-vocab precompute of P and A1B.
// ---------------------------------------------------------------------------
__global__ void __launch_bounds__(256) k_pre(const float* __restrict__ u2e)
{
    __shared__ u32 sBF[4096];        // L=3 (W1) and L=4 frag blocks, 16KB

    const int tid = threadIdx.x;
    {
        const uint4* src = reinterpret_cast<const uint4*>(g_Wf + 3 * 2048);
        uint4* dst = reinterpret_cast<uint4*>(sBF);
        for (int i = tid; i < 1024; i += 256) dst[i] = src[i];
    }
    __syncthreads();

    const int wid  = tid >> 5;
    const int lane = tid & 31;
    const int g    = lane >> 2;
    const int q2   = (lane & 3) << 1;

    const int wt = blockIdx.x * 8 + wid;
    if (wt >= VTILE) return;
    const int v0 = wt * 16 + g;
    const int v1 = v0 + 8;

    u32 ah[16], al[16];
    #pragma unroll
    for (int rr = 0; rr < 2; rr++) {
        const float* Mr = u2e + (size_t)(wt*16 + g + rr*8) * 64;
        #pragma unroll
        for (int kt = 0; kt < 4; kt++) {
            const int c0 = kt*16 + q2;
            const float2 pa = *reinterpret_cast<const float2*>(Mr + c0);
            const float2 pb = *reinterpret_cast<const float2*>(Mr + c0 + 8);
            split2h(pa.x, pa.y, ah[kt*4 + rr],     al[kt*4 + rr]);
            split2h(pb.x, pb.y, ah[kt*4 + 2 + rr], al[kt*4 + 2 + rr]);
        }
    }

    float D[32];
    gemm64(D, ah, al, sBF, lane);
    #pragma unroll
    for (int nt = 0; nt < 8; nt++) {
        const int c0 = nt*8 + q2;
        *reinterpret_cast<float2*>(g_P + (size_t)v0*64 + c0) = make_float2(D[nt*4+0], D[nt*4+1]);
        *reinterpret_cast<float2*>(g_P + (size_t)v1*64 + c0) = make_float2(D[nt*4+2], D[nt*4+3]);
    }
    gemm64(D, ah, al, sBF + 2048, lane);
    #pragma unroll
    for (int nt = 0; nt < 8; nt++) {
        const int c0 = nt*8 + q2;
        *reinterpret_cast<float2*>(g_A1B + (size_t)v0*64 + c0) = make_float2(D[nt*4+0], D[nt*4+1]);
        *reinterpret_cast<float2*>(g_A1B + (size_t)v1*64 + c0) = make_float2(D[nt*4+2], D[nt*4+3]);
    }
}

// ---------------------------------------------------------------------------
// Main kernel: layers 1..4 + scores. Each warp: 32 pairs (two m16 tiles).
// ---------------------------------------------------------------------------
#define DSM_U32  (6144 + 512 + 5*64)   // 6976 u32 = 27904 B
#define DSM_BYTES (DSM_U32 * 4)

__global__ void __launch_bounds__(128, 2) k_main(
    const int*   __restrict__ nodes,
    const int*   __restrict__ nidx,
    const float* __restrict__ labels,
    const float* __restrict__ w1W,
    const float* __restrict__ w1b,
    const float* __restrict__ w2b,
    const float* __restrict__ a1b,
    const float* __restrict__ a2b,
    const float* __restrict__ a3W,
    const float* __restrict__ a3b)
{
    extern __shared__ u32 dsm[];
    u32*   sBF  = dsm;                       // 6144 u32 (24KB): L=0,1,2
    float* sW1L = (float*)(dsm + 6144);      // 512
    float* sB1  = sW1L + 512;
    float* sB2  = sB1 + 64;
    float* sBa1 = sB2 + 64;
    float* sBa2 = sBa1 + 64;
    float* sA3  = sBa2 + 64;

    const int tid = threadIdx.x;
    {
        const uint4* src = reinterpret_cast<const uint4*>(g_Wf);
        uint4* dst = reinterpret_cast<uint4*>(sBF);
        for (int i = tid; i < 1536; i += 128) dst[i] = src[i];
        for (int i = tid; i < 512; i += 128) sW1L[i] = w1W[4096 + i];
        if (tid < 64) {
            sB1 [tid] = w1b[tid];
            sB2 [tid] = w2b[tid];
            sBa1[tid] = a1b[tid];
            sBa2[tid] = a2b[tid];
            sA3 [tid] = a3W[tid];
        }
    }
    __syncthreads();

    const float a3b0 = a3b[0];
    const int wid  = tid >> 5;             // 0..3
    const int lane = tid & 31;
    const int g    = lane >> 2;            // 0..7
    const int q2   = (lane & 3) << 1;      // 0,2,4,6

    for (int t = blockIdx.x; t < NTILE; t += gridDim.x) {
        const int pb = t * 128 + wid * 32 + g;   // rows pb, pb+8, pb+16, pb+24

        u32 ahA[16], alA[16], ahB[16], alB[16];

        // ================= LAYER 1 (scalar) → A fragments (2-term) ========
        #pragma unroll
        for (int rr = 0; rr < 4; rr++) {
            const int p  = pb + rr * 8;
            u32* ah = (rr < 2) ? ahA : ahB;
            u32* al = (rr < 2) ? alA : alB;
            const int sl = rr & 1;

            const int ni = __ldg(&nidx[p]);
            const float* Pr = g_P + (size_t)ni * 64;
            const float4* lv = reinterpret_cast<const float4*>(labels + (size_t)p * 8);
            const float4 la = lv[0], lb = lv[1];
            const float lab[8] = { la.x, la.y, la.z, la.w, lb.x, lb.y, lb.z, lb.w };

            #pragma unroll
            for (int kt = 0; kt < 4; kt++) {
                const int c0 = kt * 16 + q2;
                const float2 pa = *reinterpret_cast<const float2*>(Pr + c0);
                const float2 pbv = *reinterpret_cast<const float2*>(Pr + c0 + 8);
                float v0 = pa.x + sB1[c0];
                float v1 = pa.y + sB1[c0 + 1];
                float v2 = pbv.x + sB1[c0 + 8];
                float v3 = pbv.y + sB1[c0 + 9];
                #pragma unroll
                for (int j = 0; j < 8; j++) {
                    const float* wr = sW1L + j * 64 + c0;
                    v0 = fmaf(lab[j], wr[0], v0);
                    v1 = fmaf(lab[j], wr[1], v1);
                    v2 = fmaf(lab[j], wr[8], v2);
                    v3 = fmaf(lab[j], wr[9], v3);
                }
                v0 = fmaxf(v0, 0.f); v1 = fmaxf(v1, 0.f);
                v2 = fmaxf(v2, 0.f); v3 = fmaxf(v3, 0.f);
                split2h(v0, v1, ah[kt*4 + sl],     al[kt*4 + sl]);
                split2h(v2, v3, ah[kt*4 + 2 + sl], al[kt*4 + 2 + sl]);
            }
        }

        float D[64];

        // ======= LAYER 2 (2-term; o feeds output directly) ========
        gemm64x2(D, ahA, alA, ahB, alB, sBF, lane);
        #pragma unroll
        for (int nt = 0; nt < 8; nt++) {
            const int c0 = nt * 8 + q2;
            const int kt = nt >> 1, hf = nt & 1;
            #pragma unroll
            for (int half = 0; half < 2; half++) {
                const float b0 = sB2[c0], b1 = sB2[c0 + 1];
                const float v0 = fmaxf(D[nt*8 + half*4 + 0] + b0, 0.f);
                const float v1 = fmaxf(D[nt*8 + half*4 + 1] + b1, 0.f);
                const float v2 = fmaxf(D[nt*8 + half*4 + 2] + b0, 0.f);
                const float v3 = fmaxf(D[nt*8 + half*4 + 3] + b1, 0.f);
                const int r0 = pb + half * 16;
                *reinterpret_cast<float2*>(g_O + (size_t)r0 * 64 + c0)       = make_float2(v0, v1);
                *reinterpret_cast<float2*>(g_O + (size_t)(r0 + 8) * 64 + c0) = make_float2(v2, v3);
                u32* ah = half ? ahB : ahA;
                ah[kt*4 + hf*2 + 0] = pack_h2(v0, v1);   // hi only: L3 is 1-term
                ah[kt*4 + hf*2 + 1] = pack_h2(v2, v3);
            }
        }

        // ===== LAYER 3 (1-term; scores only): a = relu(o@A1a + A1B + b) ===
        const float* G[4];
        #pragma unroll
        for (int rr = 0; rr < 4; rr++)
            G[rr] = g_A1B + (size_t)__ldg(&nodes[(pb + rr * 8) / K_N]) * 64;

        gemm64x2_1t(D, ahA, ahB, sBF + 2048, lane);
        #pragma unroll
        for (int nt = 0; nt < 8; nt++) {
            const int c0 = nt * 8 + q2;
            const int kt = nt >> 1, hf = nt & 1;
            #pragma unroll
            for (int half = 0; half < 2; half++) {
                const float2 g0 = *reinterpret_cast<const float2*>(G[half*2]     + c0);
                const float2 g1 = *reinterpret_cast<const float2*>(G[half*2 + 1] + c0);
                const float b0 = sBa1[c0], b1 = sBa1[c0 + 1];
                const float v0 = fmaxf(D[nt*8 + half*4 + 0] + b0 + g0.x, 0.f);
                const float v1 = fmaxf(D[nt*8 + half*4 + 1] + b1 + g0.y, 0.f);
                const float v2 = fmaxf(D[nt*8 + half*4 + 2] + b0 + g1.x, 0.f);
                const float v3 = fmaxf(D[nt*8 + half*4 + 3] + b1 + g1.y, 0.f);
                u32* ah = half ? ahB : ahA;
                ah[kt*4 + hf*2 + 0] = pack_h2(v0, v1);
                ah[kt*4 + hf*2 + 1] = pack_h2(v2, v3);
            }
        }

        // ===== LAYER 4 (1-term): a2 = relu(a @ A2 + b); score = a2 . a3 ===
        gemm64x2_1t(D, ahA, ahB, sBF + 4096, lane);
        float s[4] = {0.f, 0.f, 0.f, 0.f};
        #pragma unroll
        for (int nt = 0; nt < 8; nt++) {
            const int c0 = nt * 8 + q2;
            const float b0 = sBa2[c0], b1 = sBa2[c0 + 1];
            const float w0 = sA3[c0],  w1 = sA3[c0 + 1];
            #pragma unroll
            for (int half = 0; half < 2; half++) {
                const float v0 = fmaxf(D[nt*8 + half*4 + 0] + b0, 0.f);
                const float v1 = fmaxf(D[nt*8 + half*4 + 1] + b1, 0.f);
                const float v2 = fmaxf(D[nt*8 + half*4 + 2] + b0, 0.f);
                const float v3 = fmaxf(D[nt*8 + half*4 + 3] + b1, 0.f);
                s[half*2]     = fmaf(v0, w0, fmaf(v1, w1, s[half*2]));
                s[half*2 + 1] = fmaf(v2, w0, fmaf(v3, w1, s[half*2 + 1]));
            }
        }
        #pragma unroll
        for (int rr = 0; rr < 4; rr++) {
            float sv = s[rr];
            sv += __shfl_xor_sync(0xffffffffu, sv, 1);
            sv += __shfl_xor_sync(0xffffffffu, sv, 2);
            if ((lane & 3) == 0) g_S[pb + rr * 8] = sv + a3b0;
        }
    }
}

// ---------------------------------------------------------------------------
// Kernel 3: masked softmax + aggregate. Weights staged in smem (no shfl in
// the load loop) + 4-way unrolled g_O loads for MLP.
// ---------------------------------------------------------------------------
__global__ void __launch_bounds__(256) k_agg(const int*   __restrict__ nodes,
                                             const int*   __restrict__ nlen,
                                             const float* __restrict__ u2e,
                                             float*       __restrict__ out)
{
    __shared__ float sw[8][64];
    const int warp = threadIdx.x >> 5;
    const int wid  = (blockIdx.x * 256 + threadIdx.x) >> 5;
    const int lane = threadIdx.x & 31;
    if (wid >= B_N) return;
    const int b   = wid;
    const int len = nlen[b];

    if (len <= 0) {
        const int node = nodes[b];
        const float2* src = reinterpret_cast<const float2*>(u2e + (size_t)node * 64);
        reinterpret_cast<float2*>(out + (size_t)b * 64)[lane] = src[lane];
        return;
    }

    const float* Sb = g_S + (size_t)b * K_N;
    float s0 = (lane      < len) ? Sb[lane]      : -3.0e38f;
    float s1 = (lane + 32 < len) ? Sb[lane + 32] : -3.0e38f;

    float m = fmaxf(s0, s1);
    #pragma unroll
    for (int o = 16; o > 0; o >>= 1) m = fmaxf(m, __shfl_xor_sync(0xffffffffu, m, o));

    const float e0 = (lane      < len) ? expf(s0 - m) : 0.f;
    const float e1 = (lane + 32 < len) ? expf(s1 - m) : 0.f;

    float ss = e0 + e1;
    #pragma unroll
    for (int o = 16; o > 0; o >>= 1) ss += __shfl_xor_sync(0xffffffffu, ss, o);

    const float inv = 1.f / ss;
    sw[warp][lane]      = e0 * inv;
    sw[warp][lane + 32] = e1 * inv;
    __syncwarp();

    const float* swp = sw[warp];
    float2 agg = make_float2(0.f, 0.f);
    const float2* Ob = reinterpret_cast<const float2*>(g_O + (size_t)b * K_N * 64);

    int k = 0;
    for (; k + 4 <= len; k += 4) {
        const float a0 = swp[k], a1 = swp[k+1], a2 = swp[k+2], a3 = swp[k+3];
        const float2 o0 = Ob[(k  )*32 + lane];
        const float2 o1 = Ob[(k+1)*32 + lane];
        const float2 o2 = Ob[(k+2)*32 + lane];
        const float2 o3 = Ob[(k+3)*32 + lane];
        agg.x = fmaf(a0,o0.x, fmaf(a1,o1.x, fmaf(a2,o2.x, fmaf(a3,o3.x, agg.x))));
        agg.y = fmaf(a0,o0.y, fmaf(a1,o1.y, fmaf(a2,o2.y, fmaf(a3,o3.y, agg.y))));
    }
    for (; k < len; k++) {
        const float ak = swp[k];
        const float2 ov = Ob[k*32 + lane];
        agg.x = fmaf(ak, ov.x, agg.x);
        agg.y = fmaf(ak, ov.y, agg.y);
    }
    reinterpret_cast<float2*>(out + (size_t)b * 64)[lane] = agg;
}

// ---------------------------------------------------------------------------
// kernel_launch
// ---------------------------------------------------------------------------
extern "C" void kernel_launch(void* const* d_in, const int* in_sizes, int n_in,
                              void* d_out, int out_size)
{
    const int*   nodes  = (const int*)  d_in[0];
    const int*   nidx   = (const int*)  d_in[1];
    const int*   nlen   = (const int*)  d_in[2];
    const float* labels = (const float*)d_in[3];
    const float* u2e    = (const float*)d_in[4];
    const float* w1W    = (const float*)d_in[5];
    const float* w1b    = (const float*)d_in[6];
    const float* w2W    = (const float*)d_in[7];
    const float* w2b    = (const float*)d_in[8];
    const float* a1W    = (const float*)d_in[9];
    const float* a1b    = (const float*)d_in[10];
    const float* a2W    = (const float*)d_in[11];
    const float* a2b    = (const float*)d_in[12];
    const float* a3W    = (const float*)d_in[13];
    const float* a3b    = (const float*)d_in[14];
    float* out = (float*)d_out;

    cudaFuncSetAttribute(k_main, cudaFuncAttributeMaxDynamicSharedMemorySize, DSM_BYTES);

    k_wfrag<<<20, 256>>>(w2W, a1W, a2W, w1W);
    k_pre  <<<(VTILE + 7) / 8, 256>>>(u2e);
    k_main <<<296, 128, DSM_BYTES>>>(nodes, nidx, labels, w1W, w1b,
                                     w2b, a1b, a2b, a3W, a3b);
    k_agg  <<<(B_N * 32 + 255) / 256, 256>>>(nodes, nlen, u2e, out);
}